// round 8
// baseline (speedup 1.0000x reference)
#include <cuda_runtime.h>
#include <cuda_bf16.h>
#include <mma.h>
#include <cstdint>

using namespace nvcuda;

// Problem constants
constexpr int B_   = 4;
constexpr int S_   = 1024;
constexpr int HID_ = 1024;
constexpr int H_   = 16;
constexpr int D_   = 64;

constexpr int M_ = B_ * S_;    // 4096 GEMM rows
constexpr int N_ = 2 * HID_;   // 2048 (Wq || Wk output dims)
constexpr int K_ = HID_;       // 1024 reduction

// Scratch: projected Q/K in [b, h, s, d] fp32 (pre-RoPE)
__device__ float4 g_q4[(size_t)B_ * H_ * S_ * D_ / 4];
__device__ float4 g_k4[(size_t)B_ * H_ * S_ * D_ / 4];
// bf16 hi/lo split operands for the tensor-core projection GEMM
__device__ __nv_bfloat16 g_a_hi[(size_t)M_ * K_];
__device__ __nv_bfloat16 g_a_lo[(size_t)M_ * K_];
__device__ __nv_bfloat16 g_b_hi[(size_t)N_ * K_];
__device__ __nv_bfloat16 g_b_lo[(size_t)N_ * K_];
// bf16 hi/lo RoPE'd Q/K for the tensor-core scores GEMM, [bh, s, d]
__device__ __nv_bfloat16 g_qh[(size_t)B_ * H_ * S_ * D_];
__device__ __nv_bfloat16 g_ql[(size_t)B_ * H_ * S_ * D_];
__device__ __nv_bfloat16 g_kh[(size_t)B_ * H_ * S_ * D_];
__device__ __nv_bfloat16 g_kl[(size_t)B_ * H_ * S_ * D_];

// ---------------------------------------------------------------------------
// cp.async helpers
// ---------------------------------------------------------------------------
__device__ __forceinline__ uint32_t smem_u32(const void* p) {
    uint32_t a;
    asm("{ .reg .u64 t; cvta.to.shared.u64 t, %1; cvt.u32.u64 %0, t; }"
        : "=r"(a) : "l"(p));
    return a;
}
__device__ __forceinline__ void cp_async16(uint32_t dst, const void* src) {
    asm volatile("cp.async.cg.shared.global [%0], [%1], 16;"
                 :: "r"(dst), "l"(src) : "memory");
}
__device__ __forceinline__ void cp_commit() {
    asm volatile("cp.async.commit_group;" ::: "memory");
}
template<int N>
__device__ __forceinline__ void cp_wait() {
    asm volatile("cp.async.wait_group %0;" :: "n"(N) : "memory");
}

// ---------------------------------------------------------------------------
// Kernel 0: split fp32 -> bf16 hi/lo for hidden (A) and Wq||Wk (B).
// ---------------------------------------------------------------------------
__global__ __launch_bounds__(256) void split_kernel(
    const float* __restrict__ hidden,
    const float* __restrict__ Wq,
    const float* __restrict__ Wk)
{
    const int a4 = M_ * K_ / 4;
    const int w4 = HID_ * K_ / 4;
    int i4 = blockIdx.x * blockDim.x + threadIdx.x;

    const float* src;
    __nv_bfloat16 *hi, *lo;
    size_t off;
    if (i4 < a4)           { src = hidden; off = (size_t)i4 * 4;        hi = g_a_hi; lo = g_a_lo; }
    else if (i4 < a4 + w4) { src = Wq;     off = (size_t)(i4 - a4) * 4; hi = g_b_hi; lo = g_b_lo; }
    else                   { src = Wk;     off = (size_t)(i4 - a4 - w4) * 4;
                             hi = g_b_hi + (size_t)HID_ * K_; lo = g_b_lo + (size_t)HID_ * K_; }

    float4 v = *(const float4*)(src + off);
    __nv_bfloat16 h0 = __float2bfloat16_rn(v.x);
    __nv_bfloat16 h1 = __float2bfloat16_rn(v.y);
    __nv_bfloat16 h2 = __float2bfloat16_rn(v.z);
    __nv_bfloat16 h3 = __float2bfloat16_rn(v.w);
    __nv_bfloat16 l0 = __float2bfloat16_rn(v.x - __bfloat162float(h0));
    __nv_bfloat16 l1 = __float2bfloat16_rn(v.y - __bfloat162float(h1));
    __nv_bfloat16 l2 = __float2bfloat16_rn(v.z - __bfloat162float(h2));
    __nv_bfloat16 l3 = __float2bfloat16_rn(v.w - __bfloat162float(h3));

    ushort4 hv, lv;
    hv.x = *(unsigned short*)&h0; hv.y = *(unsigned short*)&h1;
    hv.z = *(unsigned short*)&h2; hv.w = *(unsigned short*)&h3;
    lv.x = *(unsigned short*)&l0; lv.y = *(unsigned short*)&l1;
    lv.z = *(unsigned short*)&l2; lv.w = *(unsigned short*)&l3;
    *(ushort4*)(hi + off) = hv;
    *(ushort4*)(lo + off) = lv;
}

// ---------------------------------------------------------------------------
// Kernel 1: projection GEMM on WMMA bf16 (hi/lo 3-product, fp32 accum).
// Block tile 128x128, 8 warps (256 thr), warp tile 32x64. 2-stage cp.async.
// ---------------------------------------------------------------------------
constexpr int BM  = 128;
constexpr int BN  = 128;
constexpr int BK  = 32;
constexpr int LDP = 40;

// smem (elements): As[st][hl][BM][LDP] then Bs[st][hl][BN][LDP]
constexpr int AS_E     = 2 * 2 * BM * LDP;           // 20480
constexpr int BS_E     = 2 * 2 * BN * LDP;           // 20480
constexpr int P_SMEM_B = (AS_E + BS_E) * 2;          // 81920 bytes

__device__ __forceinline__ int as_off(int st, int hl, int r, int cc) {
    return ((st * 2 + hl) * BM + r) * LDP + cc;
}
__device__ __forceinline__ int bs_off(int st, int hl, int r, int cc) {
    return AS_E + ((st * 2 + hl) * BN + r) * LDP + cc;
}

__global__ __launch_bounds__(256, 2) void proj_mma_kernel()
{
    extern __shared__ __nv_bfloat16 psm[];

    const int tid = threadIdx.x;
    const int wid = tid >> 5;
    const int wm  = wid >> 1;     // 4 warps over m (32 rows each)
    const int wn  = wid & 1;      // 2 warps over n (64 cols each)

    const int n0 = blockIdx.x * BN;
    const int m0 = blockIdx.y * BM;

    auto load_stage = [&](int st, int kc) {
        // A: 2(hi/lo) x 128 rows x 4 chunks(16B) = 1024 -> 4 per thread
        #pragma unroll
        for (int p = 0; p < 4; p++) {
            int idx = tid + p * 256;
            int hl  = idx >> 9;
            int i2  = idx & 511;
            int r   = i2 >> 2;
            int c8  = (i2 & 3) * 8;
            const __nv_bfloat16* src = hl ? g_a_lo : g_a_hi;
            cp_async16(smem_u32(&psm[as_off(st, hl, r, c8)]),
                       src + (size_t)(m0 + r) * K_ + kc + c8);
        }
        // B: same shape
        #pragma unroll
        for (int p = 0; p < 4; p++) {
            int idx = tid + p * 256;
            int hl  = idx >> 9;
            int i2  = idx & 511;
            int r   = i2 >> 2;
            int c8  = (i2 & 3) * 8;
            const __nv_bfloat16* src = hl ? g_b_lo : g_b_hi;
            cp_async16(smem_u32(&psm[bs_off(st, hl, r, c8)]),
                       src + (size_t)(n0 + r) * K_ + kc + c8);
        }
    };

    wmma::fragment<wmma::accumulator, 16, 16, 16, float> c[2][4];
    #pragma unroll
    for (int i = 0; i < 2; i++)
        #pragma unroll
        for (int j = 0; j < 4; j++) wmma::fill_fragment(c[i][j], 0.0f);

    constexpr int NCH = K_ / BK;   // 32
    load_stage(0, 0);
    cp_commit();

    for (int ch = 0; ch < NCH; ch++) {
        const int st = ch & 1;
        if (ch + 1 < NCH) {
            load_stage(st ^ 1, (ch + 1) * BK);
            cp_commit();
            cp_wait<1>();
        } else {
            cp_wait<0>();
        }
        __syncthreads();

        #pragma unroll
        for (int ks = 0; ks < 2; ks++) {
            wmma::fragment<wmma::matrix_a, 16, 16, 16, __nv_bfloat16, wmma::row_major> ah[2], al[2];
            #pragma unroll
            for (int i = 0; i < 2; i++) {
                wmma::load_matrix_sync(ah[i], &psm[as_off(st, 0, wm * 32 + i * 16, ks * 16)], LDP);
                wmma::load_matrix_sync(al[i], &psm[as_off(st, 1, wm * 32 + i * 16, ks * 16)], LDP);
            }
            #pragma unroll
            for (int j = 0; j < 4; j++) {
                wmma::fragment<wmma::matrix_b, 16, 16, 16, __nv_bfloat16, wmma::col_major> bh, bl;
                wmma::load_matrix_sync(bh, &psm[bs_off(st, 0, wn * 64 + j * 16, ks * 16)], LDP);
                wmma::load_matrix_sync(bl, &psm[bs_off(st, 1, wn * 64 + j * 16, ks * 16)], LDP);
                #pragma unroll
                for (int i = 0; i < 2; i++) {
                    wmma::mma_sync(c[i][j], ah[i], bh, c[i][j]);
                    wmma::mma_sync(c[i][j], ah[i], bl, c[i][j]);
                    wmma::mma_sync(c[i][j], al[i], bh, c[i][j]);
                }
            }
        }
        __syncthreads();
    }

    float* outp   = (n0 < HID_) ? (float*)g_q4 : (float*)g_k4;
    const int nl0 = n0 & (HID_ - 1);

    #pragma unroll
    for (int i = 0; i < 2; i++) {
        const int m = m0 + wm * 32 + i * 16;
        const int b = m >> 10;
        const int s = m & (S_ - 1);
        #pragma unroll
        for (int j = 0; j < 4; j++) {
            const int nl = nl0 + wn * 64 + j * 16;
            const int h  = nl >> 6;
            const int d  = nl & 63;
            float* ptr = outp + (((size_t)(b * H_ + h) * S_ + s) * D_ + d);
            wmma::store_matrix_sync(ptr, c[i][j], D_, wmma::mem_row_major);
        }
    }
}

// ---------------------------------------------------------------------------
// Kernel 2: RoPE + bf16 hi/lo split.
// ---------------------------------------------------------------------------
__device__ __forceinline__ void split_store(__nv_bfloat16* hi, __nv_bfloat16* lo,
                                            size_t idx, float v) {
    __nv_bfloat16 h = __float2bfloat16_rn(v);
    __nv_bfloat16 l = __float2bfloat16_rn(v - __bfloat162float(h));
    hi[idx] = h; lo[idx] = l;
}

__global__ __launch_bounds__(256) void rope_split_kernel(
    const float* __restrict__ cosp,
    const float* __restrict__ sinp)
{
    int idx = blockIdx.x * blockDim.x + threadIdx.x;
    int d2     = idx & 31;
    int rowidx = idx >> 5;
    int s      = rowidx & (S_ - 1);

    float c  = cosp[s * D_ + d2];
    float sn = sinp[s * D_ + d2];

    const float* gq = (const float*)g_q4;
    const float* gk = (const float*)g_k4;
    size_t base = (size_t)rowidx * D_;

    float q1 = gq[base + d2], q2 = gq[base + d2 + 32];
    float qr1 = fmaf(q1, c, -q2 * sn);
    float qr2 = fmaf(q2, c,  q1 * sn);
    split_store(g_qh, g_ql, base + d2,      qr1);
    split_store(g_qh, g_ql, base + d2 + 32, qr2);

    float k1 = gk[base + d2], k2 = gk[base + d2 + 32];
    float kr1 = fmaf(k1, c, -k2 * sn);
    float kr2 = fmaf(k2, c,  k1 * sn);
    split_store(g_kh, g_kl, base + d2,      kr1);
    split_store(g_kh, g_kl, base + d2 + 32, kr2);
}

// ---------------------------------------------------------------------------
// Kernel 3 (FUSED): scores GEMM + causal softmax. 512 threads / 16 warps.
// One CTA per (bh, 32-row q group). Scores row block (32x1024 fp32) in smem;
// K tiles stream via 2-stage cp.async; softmax from smem; only final
// probabilities hit DRAM. MMA warp grid: 2 (q:16) x 8 (k:16).
// ---------------------------------------------------------------------------
constexpr int QR    = 32;
constexpr int FLD   = 72;
constexpr int SCLD  = 1032;

constexpr int SC_B   = QR * SCLD * 4;                 // 132096
constexpr int QT_B   = 2 * QR * FLD * 2;              // 9216
constexpr int KT_B   = 2 * 2 * 128 * FLD * 2;         // 73728
constexpr int F_SMEM = SC_B + QT_B + KT_B;            // 215040

__global__ __launch_bounds__(512) void fused_scores_softmax_kernel(float* __restrict__ out)
{
    extern __shared__ char fsm[];
    float*         sc = (float*)fsm;                                   // [QR][SCLD]
    __nv_bfloat16* qt = (__nv_bfloat16*)(fsm + SC_B);                  // [hl][QR][FLD]
    __nv_bfloat16* kt = (__nv_bfloat16*)(fsm + SC_B + QT_B);           // [st][hl][128][FLD]

    const int bh = blockIdx.y;
    const int qg = 31 - blockIdx.x;        // heavy q groups first
    const int q0 = qg * QR;
    const int ktmax = q0 >> 7;

    const int tid = threadIdx.x;
    const int wid = tid >> 5;
    const int lid = tid & 31;
    const int wq  = wid & 1;               // 2 warps over q (16 rows)
    const int wk  = wid >> 1;              // 8 warps over k (16 cols)

    const size_t qbase = (size_t)bh * S_ * D_ + (size_t)q0 * D_;
    const size_t kbase = (size_t)bh * S_ * D_;

    // ---- load Q rows (hi+lo): 512 chunks -> 1 per thread ----
    {
        int idx = tid;
        int hl  = idx >> 8;
        int i2  = idx & 255;
        int r   = i2 >> 3;
        int c8  = (i2 & 7) * 8;
        const __nv_bfloat16* src = hl ? g_ql : g_qh;
        cp_async16(smem_u32(&qt[(hl * QR + r) * FLD + c8]),
                   src + qbase + (size_t)r * D_ + c8);
    }

    auto load_k = [&](int st, int tile) {
        const size_t tb = kbase + (size_t)tile * 128 * D_;
        #pragma unroll
        for (int p = 0; p < 4; p++) {
            int idx = tid + p * 512;
            int hl  = idx >> 10;
            int i2  = idx & 1023;
            int r   = i2 >> 3;
            int c8  = (i2 & 7) * 8;
            const __nv_bfloat16* src = hl ? g_kl : g_kh;
            cp_async16(smem_u32(&kt[((st * 2 + hl) * 128 + r) * FLD + c8]),
                       src + tb + (size_t)r * D_ + c8);
        }
    };

    load_k(0, 0);
    cp_commit();

    // ---- MMA over needed k tiles ----
    for (int t = 0; t <= ktmax; t++) {
        const int st = t & 1;
        if (t + 1 <= ktmax) {
            load_k(st ^ 1, t + 1);
            cp_commit();
            cp_wait<1>();
        } else {
            cp_wait<0>();
        }
        __syncthreads();

        wmma::fragment<wmma::accumulator, 16, 16, 16, float> c;
        wmma::fill_fragment(c, 0.0f);

        const int kr = wk * 16;
        #pragma unroll
        for (int ks = 0; ks < 4; ks++) {
            wmma::fragment<wmma::matrix_a, 16, 16, 16, __nv_bfloat16, wmma::row_major> ah, al;
            wmma::load_matrix_sync(ah, &qt[(0 * QR + wq * 16) * FLD + ks * 16], FLD);
            wmma::load_matrix_sync(al, &qt[(1 * QR + wq * 16) * FLD + ks * 16], FLD);
            wmma::fragment<wmma::matrix_b, 16, 16, 16, __nv_bfloat16, wmma::col_major> bhf, blf;
            wmma::load_matrix_sync(bhf, &kt[((st * 2 + 0) * 128 + kr) * FLD + ks * 16], FLD);
            wmma::load_matrix_sync(blf, &kt[((st * 2 + 1) * 128 + kr) * FLD + ks * 16], FLD);
            wmma::mma_sync(c, ah, bhf, c);
            wmma::mma_sync(c, ah, blf, c);
            wmma::mma_sync(c, al, bhf, c);
        }

        wmma::store_matrix_sync(&sc[(wq * 16) * SCLD + t * 128 + kr], c,
                                SCLD, wmma::mem_row_major);
        __syncthreads();
    }

    // ---- softmax from smem (one warp per row, 2 rows per warp) ----
    for (int rr = wid; rr < QR; rr += 16) {
        const int qrow   = q0 + rr;
        const int nvalid = qrow + 1;
        const float* srow = &sc[rr * SCLD];

        float v[32];
        float m = -3.402823466e38f;
        #pragma unroll
        for (int i = 0; i < 8; i++) {
            const int col = lid * 4 + i * 128;
            float4 f = *(const float4*)(srow + col);
            v[i * 4 + 0] = f.x; v[i * 4 + 1] = f.y;
            v[i * 4 + 2] = f.z; v[i * 4 + 3] = f.w;
            #pragma unroll
            for (int e = 0; e < 4; e++)
                if (col + e < nvalid) m = fmaxf(m, v[i * 4 + e]);
        }
        #pragma unroll
        for (int o = 16; o > 0; o >>= 1)
            m = fmaxf(m, __shfl_xor_sync(0xFFFFFFFFu, m, o));
        m *= 0.125f;

        float ssum = 0.f;
        #pragma unroll
        for (int i = 0; i < 8; i++) {
            const int col = lid * 4 + i * 128;
            #pragma unroll
            for (int e = 0; e < 4; e++) {
                float ex = (col + e < nvalid) ? __expf(fmaf(v[i * 4 + e], 0.125f, -m)) : 0.f;
                v[i * 4 + e] = ex;
                ssum += ex;
            }
        }
        #pragma unroll
        for (int o = 16; o > 0; o >>= 1)
            ssum += __shfl_xor_sync(0xFFFFFFFFu, ssum, o);
        const float inv = 1.0f / ssum;

        float* orow = out + ((size_t)bh * S_ + qrow) * S_;
        #pragma unroll
        for (int i = 0; i < 8; i++) {
            const int col = lid * 4 + i * 128;
            float4 f = make_float4(v[i * 4 + 0] * inv, v[i * 4 + 1] * inv,
                                   v[i * 4 + 2] * inv, v[i * 4 + 3] * inv);
            *(float4*)(orow + col) = f;
        }
    }
}

// ---------------------------------------------------------------------------
// Launch
// ---------------------------------------------------------------------------
extern "C" void kernel_launch(void* const* d_in, const int* in_sizes, int n_in,
                              void* d_out, int out_size)
{
    const float* hidden = (const float*)d_in[0];
    const float* cosp   = (const float*)d_in[1];
    const float* sinp   = (const float*)d_in[2];
    const float* Wq     = (const float*)d_in[n_in - 2];
    const float* Wk     = (const float*)d_in[n_in - 1];
    float* out          = (float*)d_out;

    cudaFuncSetAttribute(proj_mma_kernel,
                         cudaFuncAttributeMaxDynamicSharedMemorySize, P_SMEM_B);
    cudaFuncSetAttribute(fused_scores_softmax_kernel,
                         cudaFuncAttributeMaxDynamicSharedMemorySize, F_SMEM);

    // 0. fp32 -> bf16 hi/lo split of A and W
    int total4 = (M_ * K_ + N_ * K_) / 4;
    split_kernel<<<total4 / 256, 256>>>(hidden, Wq, Wk);

    // 1. Projection GEMM on tensor cores
    dim3 g1(N_ / BN, M_ / BM);
    proj_mma_kernel<<<g1, 256, P_SMEM_B>>>();

    // 2. RoPE + hi/lo split for scores operands
    rope_split_kernel<<<(B_ * H_ * S_ * 32) / 256, 256>>>(cosp, sinp);

    // 3. Fused scores GEMM + causal softmax -> final probabilities
    dim3 g3(S_ / QR, B_ * H_);
    fused_scores_softmax_kernel<<<g3, 512, F_SMEM>>>(out);
}